// round 8
// baseline (speedup 1.0000x reference)
#include <cuda_runtime.h>
#include <cstdint>

namespace {

constexpr unsigned FULL = 0xffffffffu;

// ---------------------------------------------------------------------------
// GF(2) 8x8 matrix algebra (constexpr) — validated rounds 4-7.
// X basis: RX -> RZ, CNOT ring -> linear map P.
// <Z7> = (1/256) sum_v cos( sum_{active g} theta_g * (-1)^{par(a_g & v)} ).
// Embed gates collapse to qubits {0,4} (P^{-4} e7 = 0x11) => data phase is
// +-x0 +- x4; the 256-term sum factors through 4 weight-only coset sums.
// ---------------------------------------------------------------------------

struct M8 { uint8_t r[8]; };

__host__ __device__ constexpr M8 makeP() {
    M8 P{};
    for (int q = 0; q < 7; ++q) P.r[q] = uint8_t((1u << q) | (1u << (q + 1)));
    P.r[7] = uint8_t((1u << 7) | 3u);
    return P;
}
__host__ __device__ constexpr M8 ident() {
    M8 I{};
    for (int q = 0; q < 8; ++q) I.r[q] = uint8_t(1u << q);
    return I;
}
__host__ __device__ constexpr M8 matmul(const M8& A, const M8& B) {
    M8 C{};
    for (int q = 0; q < 8; ++q) {
        uint8_t row = 0;
        for (int k = 0; k < 8; ++k)
            if ((A.r[q] >> k) & 1u) row ^= B.r[k];
        C.r[q] = row;
    }
    return C;
}
__host__ __device__ constexpr M8 inverse(const M8& A) {
    unsigned m[8] = {};
    for (int q = 0; q < 8; ++q) m[q] = (unsigned)A.r[q] | (1u << (8 + q));
    for (int col = 0; col < 8; ++col) {
        int piv = col;
        while (!((m[piv] >> col) & 1u)) ++piv;
        unsigned t = m[col]; m[col] = m[piv]; m[piv] = t;
        for (int r = 0; r < 8; ++r)
            if (r != col && ((m[r] >> col) & 1u)) m[r] ^= m[col];
    }
    M8 R{};
    for (int q = 0; q < 8; ++q) R.r[q] = uint8_t(m[q] >> 8);
    return R;
}
__host__ __device__ constexpr M8 Pinv_pow(int k) {
    M8 Pi = inverse(makeP());
    M8 R = ident();
    for (int i = 0; i < k; ++i) R = matmul(Pi, R);
    return R;
}

struct WGates { int n; uint8_t a[32]; uint8_t idx[32]; };
__host__ __device__ constexpr WGates makeWG() {
    WGates G{};
    for (int l = 0; l < 4; ++l) {
        M8 A = Pinv_pow(4 - l);
        for (int q = 0; q < 8; ++q)
            if ((A.r[q] >> 7) & 1u) {
                G.a[G.n] = A.r[q];
                G.idx[G.n] = uint8_t(l * 8 + q);
                ++G.n;
            }
    }
    return G;
}
struct XGates { int n; uint8_t a[8]; uint8_t q[8]; };
__host__ __device__ constexpr XGates makeXG() {
    XGates G{};
    M8 A = Pinv_pow(4);
    for (int q = 0; q < 8; ++q)
        if ((A.r[q] >> 7) & 1u) {
            G.a[G.n] = A.r[q];
            G.q[G.n] = uint8_t(q);
            ++G.n;
        }
    return G;
}

// Sign-word columns: bit g of COL[i] = bit i of gate mask a_g.
struct Cols { uint32_t c[8]; };
__host__ __device__ constexpr Cols makeCols() {
    Cols C{};
    WGates G = makeWG();
    for (int i = 0; i < 8; ++i)
        for (int g = 0; g < G.n; ++g)
            if ((G.a[g] >> i) & 1u) C.c[i] |= 1u << g;
    return C;
}

__device__ __forceinline__ void cw_sincos(float S, float& sv, float& cv) {
    const float k = rintf(S * 0.15915494309189535f);
    float r = fmaf(k, -6.283185482025146484f, S);
    r = fmaf(k, 1.7484556000744885e-7f, r);
    __sincosf(r, &sv, &cv);
}

// Per-channel table: {A, B, D, E} scaled by 1/256.
__device__ float4 g_tab4[4];

// ---- Kernel 1: weight-only coset sums (1 block, 1024 threads). ----
__global__ __launch_bounds__(1024)
void build_tab(const float* __restrict__ w) {
    constexpr WGates WG = makeWG();
    constexpr XGates XG = makeXG();
    constexpr Cols CL = makeCols();
    static_assert(XG.n == 2, "embed collapse assumption violated");
    constexpr int MA = XG.a[0];
    constexpr int MB = XG.a[1];

    __shared__ float s_w[128];
    __shared__ float s_part[32][4];

    const int tid = threadIdx.x;
    const int lane = tid & 31;
    const int wid = tid >> 5;

    if (tid < 128) s_w[tid] = __ldg(&w[tid]);
    __syncthreads();

    const int c = tid >> 8;
    const int v = tid & 255;

    uint32_t sw = 0;
#pragma unroll
    for (int i = 0; i < 8; ++i)
        if ((v >> i) & 1) sw ^= CL.c[i];

    float S = 0.f;
#pragma unroll
    for (int g = 0; g < WG.n; ++g) {
        const float th = s_w[c * 32 + (int)WG.idx[g]];
        S += __int_as_float(__float_as_int(th) ^ (((sw >> g) & 1u) << 31));
    }

    float sv, cv;
    cw_sincos(S, sv, cv);

    const int pA = __popc(MA & v) & 1;
    const int pB = __popc(MB & v) & 1;
    const float sg = pA ? -sv : sv;
    const bool same = (pA == pB);
    float A = same ? cv : 0.f;
    float B = same ? sg : 0.f;
    float D = same ? 0.f : cv;
    float E = same ? 0.f : sg;

#pragma unroll
    for (int off = 16; off > 0; off >>= 1) {
        A += __shfl_xor_sync(FULL, A, off);
        B += __shfl_xor_sync(FULL, B, off);
        D += __shfl_xor_sync(FULL, D, off);
        E += __shfl_xor_sync(FULL, E, off);
    }
    if (lane == 0) {
        s_part[wid][0] = A; s_part[wid][1] = B;
        s_part[wid][2] = D; s_part[wid][3] = E;
    }
    __syncthreads();
    if (tid < 4) {
        float4 t;
        float* tp = &t.x;
#pragma unroll
        for (int comp = 0; comp < 4; ++comp) {
            float acc = 0.f;
#pragma unroll
            for (int k = 0; k < 8; ++k) acc += s_part[tid * 8 + k][comp];
            tp[comp] = acc * (1.f / 256.f);
        }
        g_tab4[tid] = t;
    }
}

// ---- Kernel 2: pixel map, no barriers, no shared. ----
constexpr int kPixThreads = 128;
constexpr int kPixBlocks = 8192 / kPixThreads;   // 64 blocks

__global__ __launch_bounds__(kPixThreads)
void pixel_pass(const float* __restrict__ x, float* __restrict__ out) {
    constexpr XGates XG = makeXG();
    constexpr int q0 = XG.q[0], q1 = XG.q[1];
    constexpr int c0 = q0 >> 2, d0i = (q0 >> 1) & 1, d0j = q0 & 1;
    constexpr int c1 = q1 >> 2, d1i = (q1 >> 1) & 1, d1j = q1 & 1;

    const int pixel = blockIdx.x * kPixThreads + threadIdx.x;
    const int b = pixel >> 12;
    const int i = (pixel >> 6) & 63;
    const int j = pixel & 63;

    const float x0 =
        __ldg(&x[((b * 2 + c0) * 128 + (2 * i + d0i)) * 128 + (2 * j + d0j)]);
    const float x1 =
        __ldg(&x[((b * 2 + c1) * 128 + (2 * i + d1i)) * 128 + (2 * j + d1j)]);

    const float4 t0 = __ldg(&g_tab4[0]);
    const float4 t1 = __ldg(&g_tab4[1]);
    const float4 t2 = __ldg(&g_tab4[2]);
    const float4 t3 = __ldg(&g_tab4[3]);

    float sp, cp, sm, cm;
    cw_sincos(x0 + x1, sp, cp);
    cw_sincos(x0 - x1, sm, cm);

    const int base = ((b * 4) * 64 + i) * 64 + j;
    out[base] =
        fmaf(t0.x, cp, fmaf(-t0.y, sp, fmaf(t0.z, cm, -t0.w * sm)));
    out[base + 4096] =
        fmaf(t1.x, cp, fmaf(-t1.y, sp, fmaf(t1.z, cm, -t1.w * sm)));
    out[base + 2 * 4096] =
        fmaf(t2.x, cp, fmaf(-t2.y, sp, fmaf(t2.z, cm, -t2.w * sm)));
    out[base + 3 * 4096] =
        fmaf(t3.x, cp, fmaf(-t3.y, sp, fmaf(t3.z, cm, -t3.w * sm)));
}

}  // namespace

extern "C" void kernel_launch(void* const* d_in, const int* /*in_sizes*/, int /*n_in*/,
                              void* d_out, int /*out_size*/) {
    const float* x = (const float*)d_in[0];
    const float* w = (const float*)d_in[1];
    float* out = (float*)d_out;
    build_tab<<<1, 1024>>>(w);
    pixel_pass<<<kPixBlocks, kPixThreads>>>(x, out);
}

// round 9
// speedup vs baseline: 1.3077x; 1.3077x over previous
#include <cuda_runtime.h>
#include <cstdint>

namespace {

constexpr unsigned FULL = 0xffffffffu;

// ---------------------------------------------------------------------------
// GF(2) 8x8 matrix algebra (constexpr) — validated rounds 4-8.
// X basis: RX -> RZ, CNOT ring -> linear map P.
// <Z7> = (1/256) sum_v cos( sum_{active g} theta_g * (-1)^{par(a_g & v)} ).
// Embed gates collapse to qubits {0,4} (P^{-4} e7 = 0x11) => data phase is
// +-x0 +- x4; the 256-term sum factors through 4 weight-only coset sums:
//   out_c = A_c cos(x0+x4) - B_c sin(x0+x4) + D_c cos(x0-x4) - E_c sin(x0-x4)
// ---------------------------------------------------------------------------

struct M8 { uint8_t r[8]; };

__host__ __device__ constexpr M8 makeP() {
    M8 P{};
    for (int q = 0; q < 7; ++q) P.r[q] = uint8_t((1u << q) | (1u << (q + 1)));
    P.r[7] = uint8_t((1u << 7) | 3u);
    return P;
}
__host__ __device__ constexpr M8 ident() {
    M8 I{};
    for (int q = 0; q < 8; ++q) I.r[q] = uint8_t(1u << q);
    return I;
}
__host__ __device__ constexpr M8 matmul(const M8& A, const M8& B) {
    M8 C{};
    for (int q = 0; q < 8; ++q) {
        uint8_t row = 0;
        for (int k = 0; k < 8; ++k)
            if ((A.r[q] >> k) & 1u) row ^= B.r[k];
        C.r[q] = row;
    }
    return C;
}
__host__ __device__ constexpr M8 inverse(const M8& A) {
    unsigned m[8] = {};
    for (int q = 0; q < 8; ++q) m[q] = (unsigned)A.r[q] | (1u << (8 + q));
    for (int col = 0; col < 8; ++col) {
        int piv = col;
        while (!((m[piv] >> col) & 1u)) ++piv;
        unsigned t = m[col]; m[col] = m[piv]; m[piv] = t;
        for (int r = 0; r < 8; ++r)
            if (r != col && ((m[r] >> col) & 1u)) m[r] ^= m[col];
    }
    M8 R{};
    for (int q = 0; q < 8; ++q) R.r[q] = uint8_t(m[q] >> 8);
    return R;
}
__host__ __device__ constexpr M8 Pinv_pow(int k) {
    M8 Pi = inverse(makeP());
    M8 R = ident();
    for (int i = 0; i < k; ++i) R = matmul(Pi, R);
    return R;
}

struct WGates { int n; uint8_t a[32]; uint8_t idx[32]; };
__host__ __device__ constexpr WGates makeWG() {
    WGates G{};
    for (int l = 0; l < 4; ++l) {
        M8 A = Pinv_pow(4 - l);
        for (int q = 0; q < 8; ++q)
            if ((A.r[q] >> 7) & 1u) {
                G.a[G.n] = A.r[q];
                G.idx[G.n] = uint8_t(l * 8 + q);
                ++G.n;
            }
    }
    return G;
}
struct XGates { int n; uint8_t a[8]; uint8_t q[8]; };
__host__ __device__ constexpr XGates makeXG() {
    XGates G{};
    M8 A = Pinv_pow(4);
    for (int q = 0; q < 8; ++q)
        if ((A.r[q] >> 7) & 1u) {
            G.a[G.n] = A.r[q];
            G.q[G.n] = uint8_t(q);
            ++G.n;
        }
    return G;
}

// Sign-word columns over the LOW 6 bits of v: bit g of COL[i] = bit i of a_g.
struct Cols { uint32_t c[6]; };
__host__ __device__ constexpr Cols makeCols() {
    Cols C{};
    WGates G = makeWG();
    for (int i = 0; i < 6; ++i)
        for (int g = 0; g < G.n; ++g)
            if ((G.a[g] >> i) & 1u) C.c[i] |= 1u << g;
    return C;
}

__device__ __forceinline__ void cw_sincos(float S, float& sv, float& cv) {
    const float k = rintf(S * 0.15915494309189535f);
    float r = fmaf(k, -6.283185482025146484f, S);
    r = fmaf(k, 1.7484556000744885e-7f, r);
    __sincosf(r, &sv, &cv);
}

constexpr int kThreads = 256;
constexpr int kPixPerBlock = 64;
constexpr int kBlocks = 8192 / kPixPerBlock;   // 128 blocks, one wave

__global__ __launch_bounds__(kThreads)
void qconv_fused(const float* __restrict__ x, const float* __restrict__ w,
                 float* __restrict__ out) {
    constexpr WGates WG = makeWG();
    constexpr XGates XG = makeXG();
    constexpr Cols CL = makeCols();
    static_assert(XG.n == 2, "embed collapse assumption violated");
    constexpr int MA = XG.a[0];
    constexpr int MB = XG.a[1];

    __shared__ float s_part[8][4];
    __shared__ float s_tab[4][4];   // per channel: A, B, D, E (x 1/256)

    const int tid = threadIdx.x;
    const int lane = tid & 31;
    const int wid = tid >> 5;

    // ---- Prefetch pixel inputs (tid < 64): overlap DRAM with phase 1. ----
    float x0 = 0.f, x1 = 0.f;
    int base = 0;
    if (tid < kPixPerBlock) {
        const int pixel = blockIdx.x * kPixPerBlock + tid;
        const int b = pixel >> 12;
        const int i = (pixel >> 6) & 63;
        const int j = pixel & 63;
        constexpr int q0 = XG.q[0], q1 = XG.q[1];
        constexpr int c0 = q0 >> 2, d0i = (q0 >> 1) & 1, d0j = q0 & 1;
        constexpr int c1 = q1 >> 2, d1i = (q1 >> 1) & 1, d1j = q1 & 1;
        x0 = __ldg(&x[((b * 2 + c0) * 128 + (2 * i + d0i)) * 128 + (2 * j + d0j)]);
        x1 = __ldg(&x[((b * 2 + c1) * 128 + (2 * i + d1i)) * 128 + (2 * j + d1j)]);
        base = ((b * 4) * 64 + i) * 64 + j;
    }

    // ---- Phase 1: channel c = tid>>6, low bits vt = tid&63; high 2 bits
    // of v handled via Walsh split. Weights read directly (broadcast LDG). ----
    const int c = tid >> 6;
    const int vt = tid & 63;

    // 26 gate signs for the low 6 bits at once.
    uint32_t sw = 0;
#pragma unroll
    for (int i = 0; i < 6; ++i)
        if ((vt >> i) & 1) sw ^= CL.c[i];

    // Group partial sums by (bit6, bit7) of gate mask.
    float T0 = 0.f, T1 = 0.f, T2 = 0.f, T3 = 0.f;
#pragma unroll
    for (int g = 0; g < WG.n; ++g) {
        const float th = __ldg(&w[c * 32 + (int)WG.idx[g]]);
        const float sth =
            __int_as_float(__float_as_int(th) ^ (((sw >> g) & 1u) << 31));
        constexpr_grp_add:;
        const int grp = ((int)WG.a[g] >> 6) & 3;   // compile-time constant
        if (grp == 0) T0 += sth;
        else if (grp == 1) T1 += sth;
        else if (grp == 2) T2 += sth;
        else T3 += sth;
    }

    float A = 0.f, B = 0.f, D = 0.f, E = 0.f;
#pragma unroll
    for (int k = 0; k < 4; ++k) {
        const float f1 = (k & 1) ? -T1 : T1;
        const float f2 = (k & 2) ? -T2 : T2;
        const float f3 = (((k ^ (k >> 1)) & 1)) ? -T3 : T3;
        const float S = T0 + f1 + f2 + f3;
        float sv, cv;
        cw_sincos(S, sv, cv);
        const int v = vt | (k << 6);
        const int pA = __popc(MA & v) & 1;
        const int pB = __popc(MB & v) & 1;
        const float sg = pA ? -sv : sv;
        if (pA == pB) { A += cv; B += sg; }
        else          { D += cv; E += sg; }
    }

#pragma unroll
    for (int off = 16; off > 0; off >>= 1) {
        A += __shfl_xor_sync(FULL, A, off);
        B += __shfl_xor_sync(FULL, B, off);
        D += __shfl_xor_sync(FULL, D, off);
        E += __shfl_xor_sync(FULL, E, off);
    }
    if (lane == 0) {
        s_part[wid][0] = A; s_part[wid][1] = B;
        s_part[wid][2] = D; s_part[wid][3] = E;
    }
    __syncthreads();
    if (tid < 16) {
        const int cc = tid >> 2, comp = tid & 3;
        s_tab[cc][comp] =
            (s_part[2 * cc][comp] + s_part[2 * cc + 1][comp]) * (1.f / 256.f);
    }
    __syncthreads();

    // ---- Phase 2: one output pixel per thread (tid < 64). ----
    if (tid < kPixPerBlock) {
        float sp, cp, sm, cm;
        cw_sincos(x0 + x1, sp, cp);
        cw_sincos(x0 - x1, sm, cm);
#pragma unroll
        for (int oc = 0; oc < 4; ++oc) {
            const float r = fmaf(s_tab[oc][0], cp,
                            fmaf(-s_tab[oc][1], sp,
                            fmaf(s_tab[oc][2], cm, -s_tab[oc][3] * sm)));
            out[base + oc * 4096] = r;
        }
    }
}

}  // namespace

extern "C" void kernel_launch(void* const* d_in, const int* /*in_sizes*/, int /*n_in*/,
                              void* d_out, int /*out_size*/) {
    const float* x = (const float*)d_in[0];
    const float* w = (const float*)d_in[1];
    float* out = (float*)d_out;
    qconv_fused<<<kBlocks, kThreads>>>(x, w, out);
}